// round 11
// baseline (speedup 1.0000x reference)
#include <cuda_runtime.h>

// Problem constants
#define BB 8
#define CC 256
#define HH 128
#define WW 128
#define HWc (HH * WW)   // 16384 = 2^14

// Scratch for sampling coordinates (px, py per (b,h,w)) — device globals, no allocs.
__device__ float g_px[BB * HH * WW];
__device__ float g_py[BB * HH * WW];

// ---------------------------------------------------------------------------
// Kernel A: offset conv (256 -> 2, 3x3, pad 1) + clip -> (px, py) scratch.
// grid  = (H/8, B), block = 256 threads.
// Tile: 128 wide x 8 high. Thread (txl = tid&31, ty = tid>>5) computes 4
// adjacent-w pixels: w = txl*4 + j, h = h0 + ty.
// Per channel pair: cooperative smem tile load (10 x 130 with zero halo),
// then vectorized LDS reads + register FMAs. Weights staged in smem,
// float4-padded so each channel's 9 taps load as 2xLDS.128 + 1xLDS.32.
// ---------------------------------------------------------------------------
__global__ __launch_bounds__(256)
void offset_conv_kernel(const float* __restrict__ x,
                        const float* __restrict__ w_conv,
                        const float* __restrict__ b_conv) {
    __shared__ __align__(16) float ws4[CC][2][12];   // [c][o][k(pad 12)] = 24 KB
    __shared__ __align__(16) float xt[2][10][136];   // 2 channels, padded rows = 10.6 KB

    const int tid = threadIdx.x;
    const int txl = tid & 31;    // w-group (4 pixels each)
    const int ty  = tid >> 5;    // row within tile, 0..7
    const int h0  = blockIdx.x * 8;
    const int b   = blockIdx.y;

    // Stage weights: w_conv layout [o][c][3][3] flat (o*2304 + c*9 + k)
    for (int i = tid; i < 4608; i += 256) {
        int o = i / 2304;
        int rem = i - o * 2304;
        int c = rem / 9;
        int k = rem - c * 9;
        ws4[c][o][k] = w_conv[i];
    }

    float acc0[4] = {0.f, 0.f, 0.f, 0.f};
    float acc1[4] = {0.f, 0.f, 0.f, 0.f};

    const float* xb = x + (size_t)b * CC * HWc;

    for (int cb = 0; cb < CC; cb += 2) {
        // Load two channel tiles (10 rows x 130 cols, zero-padded halo)
        #pragma unroll
        for (int cc = 0; cc < 2; cc++) {
            const float* xc = xb + (size_t)(cb + cc) * HWc;
            for (int i = tid; i < 1300; i += 256) {
                int r   = i / 130;
                int col = i - r * 130;
                int gh = h0 - 1 + r;
                int gw = col - 1;
                float v = 0.f;
                if ((unsigned)gh < HH && (unsigned)gw < WW)
                    v = xc[gh * WW + gw];
                xt[cc][r][col] = v;
            }
        }
        __syncthreads();   // also orders the one-time ws4 writes before first compute

        #pragma unroll
        for (int cc = 0; cc < 2; cc++) {
            const int c = cb + cc;
            // weights for this channel (broadcast LDS, vectorized)
            float4 a0 = *(const float4*)&ws4[c][0][0];
            float4 a1 = *(const float4*)&ws4[c][0][4];
            float  a2 = ws4[c][0][8];
            float4 c0 = *(const float4*)&ws4[c][1][0];
            float4 c1 = *(const float4*)&ws4[c][1][4];
            float  c2 = ws4[c][1][8];
            float w0[9] = {a0.x, a0.y, a0.z, a0.w, a1.x, a1.y, a1.z, a1.w, a2};
            float w1[9] = {c0.x, c0.y, c0.z, c0.w, c1.x, c1.y, c1.z, c1.w, c2};

            // x window: 3 rows x 6 cols covering pixels w = 4*txl .. 4*txl+3
            float v[3][6];
            #pragma unroll
            for (int r = 0; r < 3; r++) {
                const float* row = &xt[cc][ty + r][txl * 4];
                float4 p = *(const float4*)row;
                float2 q = *(const float2*)(row + 4);
                v[r][0] = p.x; v[r][1] = p.y; v[r][2] = p.z;
                v[r][3] = p.w; v[r][4] = q.x; v[r][5] = q.y;
            }

            #pragma unroll
            for (int j = 0; j < 4; j++) {
                #pragma unroll
                for (int dh = 0; dh < 3; dh++) {
                    #pragma unroll
                    for (int dw = 0; dw < 3; dw++) {
                        float xv = v[dh][j + dw];
                        acc0[j] = fmaf(w0[dh * 3 + dw], xv, acc0[j]);
                        acc1[j] = fmaf(w1[dh * 3 + dw], xv, acc1[j]);
                    }
                }
            }
        }
        __syncthreads();   // protect xt before next iteration's load
    }

    // Epilogue: px = clip(h + off0 + b0, 0, H-2); py = clip(w + off1 + b1, 0, W-2)
    const float bc0 = b_conv[0];
    const float bc1 = b_conv[1];
    const int h = h0 + ty;
    #pragma unroll
    for (int j = 0; j < 4; j++) {
        int w = txl * 4 + j;
        float px = (float)h + acc0[j] + bc0;
        float py = (float)w + acc1[j] + bc1;
        px = fminf(fmaxf(px, 0.f), (float)(HH - 2));
        py = fminf(fmaxf(py, 0.f), (float)(WW - 2));
        int pi = (b * HH + h) * WW + w;
        g_px[pi] = px;
        g_py[pi] = py;
    }
}

// ---------------------------------------------------------------------------
// Kernel B: bilinear sampling.
// Each thread handles 4 consecutive channels of one (b,h,w) pixel.
// gid = ((b*64 + cg) << 14) + pix; lanes differ in pix -> adjacent w, so
// both scratch reads and output stores are coalesced, and the gather lanes
// span only a few cache lines (offsets are small).
// ---------------------------------------------------------------------------
__global__ __launch_bounds__(256)
void bilinear_sample_kernel(const float* __restrict__ x,
                            float* __restrict__ out) {
    int gid  = blockIdx.x * 256 + threadIdx.x;
    int pix  = gid & (HWc - 1);
    int rest = gid >> 14;        // b*64 + cg
    int cg   = rest & 63;
    int b    = rest >> 6;

    float px = g_px[(b << 14) + pix];
    float py = g_py[(b << 14) + pix];

    float fx = floorf(px);
    float fy = floorf(py);
    float dx = px - fx;          // in [0,1)
    float dy = py - fy;
    int qx0 = (int)fx;
    int qy0 = (int)fy;

    // base plane pointer for channel c0 = cg*4
    size_t plane0 = ((size_t)b * CC + (cg << 2)) << 14;
    const float* xp = x + plane0 + (qx0 * WW + qy0);
    float* op = out + plane0 + pix;

    #pragma unroll
    for (int j = 0; j < 4; j++) {
        const float* p = xp + ((size_t)j << 14);
        float x00 = __ldg(p);            // (qx0, qy0)
        float x01 = __ldg(p + 1);        // (qx0, qy1)
        float x10 = __ldg(p + WW);       // (qx1, qy0)
        float x11 = __ldg(p + WW + 1);   // (qx1, qy1)
        float top = fmaf(dy, x01 - x00, x00);
        float bot = fmaf(dy, x11 - x10, x10);
        op[(size_t)j << 14] = fmaf(dx, bot - top, top);
    }
}

// ---------------------------------------------------------------------------
// Launch
// ---------------------------------------------------------------------------
extern "C" void kernel_launch(void* const* d_in, const int* in_sizes, int n_in,
                              void* d_out, int out_size) {
    const float* x      = (const float*)d_in[0];   // [8,256,128,128]
    const float* w_conv = (const float*)d_in[1];   // [2,256,3,3]
    const float* b_conv = (const float*)d_in[2];   // [2]
    float* out = (float*)d_out;                    // [8,256,128,128,1]

    offset_conv_kernel<<<dim3(HH / 8, BB), 256>>>(x, w_conv, b_conv);

    int total_threads = BB * (CC / 4) * HWc;       // 8,388,608
    bilinear_sample_kernel<<<total_threads / 256, 256>>>(x, out);
}

// round 12
// speedup vs baseline: 4.2010x; 4.2010x over previous
#include <cuda_runtime.h>

// Problem constants
#define BB 8
#define CC 256
#define HH 128
#define WW 128
#define HWc (HH * WW)      // 16384
#define NPIX (BB * HWc)    // 131072
#define CSPLIT 8
#define CPB (CC / CSPLIT)  // 32 channels per block

// Device scratch (no allocs allowed). Partials per channel-split, then px/py.
__device__ float g_part0[CSPLIT * NPIX];   // 4 MB
__device__ float g_part1[CSPLIT * NPIX];   // 4 MB
__device__ float g_px[NPIX];
__device__ float g_py[NPIX];

// ---- packed f32x2 helpers (sm_103a FFMA2 is PTX-only) ----------------------
__device__ __forceinline__ unsigned long long pack_dup(float x) {
    unsigned long long r;
    asm("mov.b64 %0, {%1, %1};" : "=l"(r) : "r"(__float_as_uint(x)));
    return r;
}
__device__ __forceinline__ void unpack2(unsigned long long v, float& lo, float& hi) {
    unsigned int a, b;
    asm("mov.b64 {%0, %1}, %2;" : "=r"(a), "=r"(b) : "l"(v));
    lo = __uint_as_float(a);
    hi = __uint_as_float(b);
}
#define FMA2(acc, a, b) \
    asm("fma.rn.f32x2 %0, %1, %2, %0;" : "+l"(acc) : "l"(a), "l"(b))

// ---------------------------------------------------------------------------
// Kernel A: offset conv partials. grid=(H/8, B, CSPLIT), block=256.
// Block handles 32 channels x (8-row x 128-col) tile. Thread (txl=tid&31,
// ty=tid>>5) computes 4 adjacent-w pixels. Per channel pair: cooperative
// smem tile (10 x 130 zero halo), then packed-f32x2 FMAs (both conv outputs
// share x operands). Partials written as float4 to g_part{0,1}.
// ---------------------------------------------------------------------------
__global__ __launch_bounds__(256)
void offset_conv_partial(const float* __restrict__ x,
                         const float* __restrict__ w_conv) {
    __shared__ __align__(16) float2 ws2[CPB][12];    // (w0,w1) pairs, 3 KB
    __shared__ __align__(16) float  xt[2][10][136];  // 2 channels, ~10.6 KB

    const int tid = threadIdx.x;
    const int txl = tid & 31;
    const int ty  = tid >> 5;
    const int h0  = blockIdx.x * 8;
    const int b   = blockIdx.y;
    const int c0  = blockIdx.z * CPB;

    // Stage packed weights for this block's 32 channels.
    // w_conv layout: [o][c][3][3] flat = o*2304 + c*9 + k
    for (int i = tid; i < CPB * 9; i += 256) {
        int c = i / 9;
        int k = i - c * 9;
        ws2[c][k] = make_float2(w_conv[(c0 + c) * 9 + k],
                                w_conv[2304 + (c0 + c) * 9 + k]);
    }

    unsigned long long accp[4] = {0ull, 0ull, 0ull, 0ull};  // (acc0, acc1) pairs

    const float* xb = x + ((size_t)b * CC + c0) * HWc;

    for (int cb = 0; cb < CPB; cb += 2) {
        // Cooperative load of two channel tiles (10 x 130, zero halo)
        #pragma unroll
        for (int cc = 0; cc < 2; cc++) {
            const float* xc = xb + (size_t)(cb + cc) * HWc;
            for (int i = tid; i < 1300; i += 256) {
                int r   = i / 130;
                int col = i - r * 130;
                int gh = h0 - 1 + r;
                int gw = col - 1;
                float v = 0.f;
                if ((unsigned)gh < HH && (unsigned)gw < WW)
                    v = xc[gh * WW + gw];
                xt[cc][r][col] = v;
            }
        }
        __syncthreads();

        #pragma unroll
        for (int cc = 0; cc < 2; cc++) {
            // 9 packed weights (LDS.64 broadcast)
            const unsigned long long* wrow =
                (const unsigned long long*)&ws2[cb + cc][0];
            unsigned long long wp[9];
            #pragma unroll
            for (int k = 0; k < 9; k++) wp[k] = wrow[k];

            // x window: 3 rows x 6 cols, vector LDS, then duplicate-pack
            unsigned long long vx[3][6];
            #pragma unroll
            for (int r = 0; r < 3; r++) {
                const float* row = &xt[cc][ty + r][txl * 4];
                float4 p = *(const float4*)row;
                float2 q = *(const float2*)(row + 4);
                vx[r][0] = pack_dup(p.x); vx[r][1] = pack_dup(p.y);
                vx[r][2] = pack_dup(p.z); vx[r][3] = pack_dup(p.w);
                vx[r][4] = pack_dup(q.x); vx[r][5] = pack_dup(q.y);
            }

            #pragma unroll
            for (int j = 0; j < 4; j++) {
                #pragma unroll
                for (int dh = 0; dh < 3; dh++) {
                    #pragma unroll
                    for (int dw = 0; dw < 3; dw++) {
                        FMA2(accp[j], wp[dh * 3 + dw], vx[dh][j + dw]);
                    }
                }
            }
        }
        __syncthreads();
    }

    // Unpack and store partials (float4, coalesced)
    float a0[4], a1[4];
    #pragma unroll
    for (int j = 0; j < 4; j++) unpack2(accp[j], a0[j], a1[j]);

    const int h   = h0 + ty;
    const int pix = (b << 14) + h * WW + txl * 4;
    const int idx = blockIdx.z * NPIX + pix;
    *(float4*)&g_part0[idx] = make_float4(a0[0], a0[1], a0[2], a0[3]);
    *(float4*)&g_part1[idx] = make_float4(a1[0], a1[1], a1[2], a1[3]);
}

// ---------------------------------------------------------------------------
// Kernel A2: reduce the 8 channel-split partials, add bias, clip -> px/py.
// ---------------------------------------------------------------------------
__global__ __launch_bounds__(256)
void offset_combine(const float* __restrict__ b_conv) {
    int p = blockIdx.x * 256 + threadIdx.x;   // 0 .. NPIX-1
    float s0 = 0.f, s1 = 0.f;
    #pragma unroll
    for (int s = 0; s < CSPLIT; s++) {
        s0 += g_part0[s * NPIX + p];
        s1 += g_part1[s * NPIX + p];
    }
    int h = (p >> 7) & (HH - 1);
    int w = p & (WW - 1);
    float px = (float)h + s0 + b_conv[0];
    float py = (float)w + s1 + b_conv[1];
    px = fminf(fmaxf(px, 0.f), (float)(HH - 2));
    py = fminf(fmaxf(py, 0.f), (float)(WW - 2));
    g_px[p] = px;
    g_py[p] = py;
}

// ---------------------------------------------------------------------------
// Kernel B: bilinear sampling. Thread = 4 consecutive channels of one pixel.
// Lanes differ in pix (adjacent w) -> coalesced scratch reads/output stores;
// gathers span few lines since offsets are small.
// ---------------------------------------------------------------------------
__global__ __launch_bounds__(256)
void bilinear_sample_kernel(const float* __restrict__ x,
                            float* __restrict__ out) {
    int gid  = blockIdx.x * 256 + threadIdx.x;
    int pix  = gid & (HWc - 1);
    int rest = gid >> 14;        // b*64 + cg
    int cg   = rest & 63;
    int b    = rest >> 6;

    float px = g_px[(b << 14) + pix];
    float py = g_py[(b << 14) + pix];

    float fx = floorf(px);
    float fy = floorf(py);
    float dx = px - fx;
    float dy = py - fy;
    int qx0 = (int)fx;
    int qy0 = (int)fy;

    size_t plane0 = ((size_t)b * CC + (cg << 2)) << 14;
    const float* xp = x + plane0 + (qx0 * WW + qy0);
    float* op = out + plane0 + pix;

    #pragma unroll
    for (int j = 0; j < 4; j++) {
        const float* p = xp + ((size_t)j << 14);
        float x00 = __ldg(p);
        float x01 = __ldg(p + 1);
        float x10 = __ldg(p + WW);
        float x11 = __ldg(p + WW + 1);
        float top = fmaf(dy, x01 - x00, x00);
        float bot = fmaf(dy, x11 - x10, x10);
        op[(size_t)j << 14] = fmaf(dx, bot - top, top);
    }
}

// ---------------------------------------------------------------------------
// Launch
// ---------------------------------------------------------------------------
extern "C" void kernel_launch(void* const* d_in, const int* in_sizes, int n_in,
                              void* d_out, int out_size) {
    const float* x      = (const float*)d_in[0];   // [8,256,128,128]
    const float* w_conv = (const float*)d_in[1];   // [2,256,3,3]
    const float* b_conv = (const float*)d_in[2];   // [2]
    float* out = (float*)d_out;                    // [8,256,128,128,1]

    offset_conv_partial<<<dim3(HH / 8, BB, CSPLIT), 256>>>(x, w_conv);
    offset_combine<<<NPIX / 256, 256>>>(b_conv);

    int total_threads = BB * (CC / 4) * HWc;       // 8,388,608
    bilinear_sample_kernel<<<total_threads / 256, 256>>>(x, out);
}

// round 14
// speedup vs baseline: 4.9590x; 1.1804x over previous
#include <cuda_runtime.h>

// Problem constants
#define BB 8
#define CC 256
#define HH 128
#define WW 128
#define HWc (HH * WW)      // 16384
#define NPIX (BB * HWc)    // 131072
#define CSPLIT 8
#define CPB (CC / CSPLIT)  // 32 channels per block

// Device scratch (no allocs allowed).
__device__ float g_part0[CSPLIT * NPIX];   // 4 MB
__device__ float g_part1[CSPLIT * NPIX];   // 4 MB
__device__ float g_px[NPIX];
__device__ float g_py[NPIX];

// ---- packed f32x2 helpers (sm_103a FFMA2 is PTX-only) ----------------------
__device__ __forceinline__ unsigned long long pack_dup(float x) {
    unsigned long long r;
    asm("mov.b64 %0, {%1, %1};" : "=l"(r) : "r"(__float_as_uint(x)));
    return r;
}
__device__ __forceinline__ void unpack2(unsigned long long v, float& lo, float& hi) {
    unsigned int a, b;
    asm("mov.b64 {%0, %1}, %2;" : "=r"(a), "=r"(b) : "l"(v));
    lo = __uint_as_float(a);
    hi = __uint_as_float(b);
}
#define FMA2(acc, a, b) \
    asm("fma.rn.f32x2 %0, %1, %2, %0;" : "+l"(acc) : "l"(a), "l"(b))

// ---------------------------------------------------------------------------
// Kernel A: offset conv partials, software-pipelined.
// grid=(H/16, B, CSPLIT)=(8,8,8), block=256. Thread (txl=tid&15, ty=tid>>4)
// computes 8 adjacent-w pixels of row h0+ty for 32 channels.
// Double-buffered smem channel-pair tiles (18 rows x 136 padded cols):
//   iter i: LDG pair i+1 -> regs | compute pair i | BAR | STS regs | BAR.
// Row layout: [3]=col -1 (zero), [4..131]=cols 0..127, [132]=col 128 (zero).
// ---------------------------------------------------------------------------
__global__ __launch_bounds__(256)
void offset_conv_partial(const float* __restrict__ x,
                         const float* __restrict__ w_conv) {
    __shared__ __align__(16) float  xt[2][2][18][136];  // ~39 KB
    __shared__ __align__(16) float2 ws2[CPB][9];        // (w0,w1) pairs

    const int tid = threadIdx.x;
    const int txl = tid & 15;    // w-group of 8 pixels
    const int ty  = tid >> 4;    // row 0..15
    const int h0  = blockIdx.x * 16;
    const int b   = blockIdx.y;
    const int c0  = blockIdx.z * CPB;

    // Stage packed weights. w_conv flat: o*2304 + c*9 + k
    // NOTE: CPB*9 = 288 > blockDim, must be a strided loop (R13 bug).
    for (int i = tid; i < CPB * 9; i += 256) {
        int c = i / 9, k = i - c * 9;
        ws2[c][k] = make_float2(w_conv[(c0 + c) * 9 + k],
                                w_conv[2304 + (c0 + c) * 9 + k]);
    }
    // Column-halo zeros (cols -1 and 128 are always outside the image).
    if (tid < 144) {
        int bf  = tid / 72;
        int rem = tid - bf * 72;
        int ch  = rem / 36; rem -= ch * 36;
        int r = rem >> 1, side = rem & 1;
        xt[bf][ch][r][side ? 132 : 3] = 0.f;
    }

    const float* xb = x + (((size_t)b * CC + c0) << 14);

    // Per-thread constant prefetch slots (division-free decode).
    int  pr_r[5], pr_c4[5], pr_ch[5];
    bool pr_v[5], pr_g[5];
    #pragma unroll
    for (int k = 0; k < 5; k++) {
        int idx = tid + (k << 8);          // 0..1279 over 2ch x 18rows x 32 float4
        pr_v[k] = idx < 1152;
        int ch = idx >= 576 ? 1 : 0;
        int ii = idx - ch * 576;
        pr_r[k]  = ii >> 5;
        pr_c4[k] = ii & 31;
        pr_ch[k] = ch;
        int gh = h0 - 1 + pr_r[k];
        pr_g[k] = pr_v[k] && ((unsigned)gh < HH);
    }

    float4 pre[5];
    auto load_pair = [&](int pair) {
        const float* base = xb + ((size_t)(pair * 2) << 14);
        #pragma unroll
        for (int k = 0; k < 5; k++) {
            float4 v = make_float4(0.f, 0.f, 0.f, 0.f);
            if (pr_g[k]) {
                int gh = h0 - 1 + pr_r[k];
                v = *(const float4*)(base + ((size_t)pr_ch[k] << 14)
                                     + gh * WW + pr_c4[k] * 4);
            }
            pre[k] = v;
        }
    };
    auto store_pair = [&](int bf) {
        #pragma unroll
        for (int k = 0; k < 5; k++)
            if (pr_v[k])
                *(float4*)&xt[bf][pr_ch[k]][pr_r[k]][4 + pr_c4[k] * 4] = pre[k];
    };

    // Prologue: fill buffer 0 with channel pair 0.
    load_pair(0);
    store_pair(0);
    __syncthreads();

    unsigned long long accp[8] = {0ull,0ull,0ull,0ull,0ull,0ull,0ull,0ull};
    const int s = txl * 8;   // window float-index base (col w0-1 at row+s+3)

    for (int i = 0; i < CPB / 2; i++) {
        const int bf = i & 1;
        const bool more = (i + 1) < (CPB / 2);
        if (more) load_pair(i + 1);   // LDGs in flight during compute

        #pragma unroll
        for (int cc = 0; cc < 2; cc++) {
            const unsigned long long* wr =
                (const unsigned long long*)&ws2[2 * i + cc][0];
            #pragma unroll
            for (int r = 0; r < 3; r++) {
                // 3 broadcast weight pairs for this tap row
                unsigned long long w0 = wr[r * 3 + 0];
                unsigned long long w1 = wr[r * 3 + 1];
                unsigned long long w2 = wr[r * 3 + 2];

                const float* row = &xt[bf][cc][ty + r][0];
                float2 e0 = *(const float2*)(row + s + 2);   // .y = col w0-1
                float4 m0 = *(const float4*)(row + s + 4);
                float4 m1 = *(const float4*)(row + s + 8);
                float2 e1 = *(const float2*)(row + s + 12);  // .x = col w0+8

                unsigned long long pv[10];
                pv[0] = pack_dup(e0.y);
                pv[1] = pack_dup(m0.x); pv[2] = pack_dup(m0.y);
                pv[3] = pack_dup(m0.z); pv[4] = pack_dup(m0.w);
                pv[5] = pack_dup(m1.x); pv[6] = pack_dup(m1.y);
                pv[7] = pack_dup(m1.z); pv[8] = pack_dup(m1.w);
                pv[9] = pack_dup(e1.x);

                #pragma unroll
                for (int j = 0; j < 8; j++) {
                    FMA2(accp[j], w0, pv[j]);
                    FMA2(accp[j], w1, pv[j + 1]);
                    FMA2(accp[j], w2, pv[j + 2]);
                }
            }
        }
        __syncthreads();               // reads of xt[bf] complete
        if (more) store_pair(bf ^ 1);  // write next pair into the other buffer
        __syncthreads();
    }

    // Epilogue: unpack and store partials (2x float4 per array, coalesced).
    float o0[8], o1[8];
    #pragma unroll
    for (int j = 0; j < 8; j++) unpack2(accp[j], o0[j], o1[j]);

    const int h   = h0 + ty;
    const int pix = (b << 14) + h * WW + txl * 8;
    const int idx = blockIdx.z * NPIX + pix;
    *(float4*)&g_part0[idx]     = make_float4(o0[0], o0[1], o0[2], o0[3]);
    *(float4*)&g_part0[idx + 4] = make_float4(o0[4], o0[5], o0[6], o0[7]);
    *(float4*)&g_part1[idx]     = make_float4(o1[0], o1[1], o1[2], o1[3]);
    *(float4*)&g_part1[idx + 4] = make_float4(o1[4], o1[5], o1[6], o1[7]);
}

// ---------------------------------------------------------------------------
// Kernel A2: reduce the 8 channel-split partials, add bias, clip -> px/py.
// ---------------------------------------------------------------------------
__global__ __launch_bounds__(256)
void offset_combine(const float* __restrict__ b_conv) {
    int p = blockIdx.x * 256 + threadIdx.x;
    float s0 = 0.f, s1 = 0.f;
    #pragma unroll
    for (int s = 0; s < CSPLIT; s++) {
        s0 += g_part0[s * NPIX + p];
        s1 += g_part1[s * NPIX + p];
    }
    int h = (p >> 7) & (HH - 1);
    int w = p & (WW - 1);
    float px = (float)h + s0 + b_conv[0];
    float py = (float)w + s1 + b_conv[1];
    px = fminf(fmaxf(px, 0.f), (float)(HH - 2));
    py = fminf(fmaxf(py, 0.f), (float)(WW - 2));
    g_px[p] = px;
    g_py[p] = py;
}

// ---------------------------------------------------------------------------
// Kernel B: bilinear sampling (unchanged — L1-bound at 68us).
// ---------------------------------------------------------------------------
__global__ __launch_bounds__(256)
void bilinear_sample_kernel(const float* __restrict__ x,
                            float* __restrict__ out) {
    int gid  = blockIdx.x * 256 + threadIdx.x;
    int pix  = gid & (HWc - 1);
    int rest = gid >> 14;        // b*64 + cg
    int cg   = rest & 63;
    int b    = rest >> 6;

    float px = g_px[(b << 14) + pix];
    float py = g_py[(b << 14) + pix];

    float fx = floorf(px);
    float fy = floorf(py);
    float dx = px - fx;
    float dy = py - fy;
    int qx0 = (int)fx;
    int qy0 = (int)fy;

    size_t plane0 = ((size_t)b * CC + (cg << 2)) << 14;
    const float* xp = x + plane0 + (qx0 * WW + qy0);
    float* op = out + plane0 + pix;

    #pragma unroll
    for (int j = 0; j < 4; j++) {
        const float* p = xp + ((size_t)j << 14);
        float x00 = __ldg(p);
        float x01 = __ldg(p + 1);
        float x10 = __ldg(p + WW);
        float x11 = __ldg(p + WW + 1);
        float top = fmaf(dy, x01 - x00, x00);
        float bot = fmaf(dy, x11 - x10, x10);
        op[(size_t)j << 14] = fmaf(dx, bot - top, top);
    }
}

// ---------------------------------------------------------------------------
// Launch
// ---------------------------------------------------------------------------
extern "C" void kernel_launch(void* const* d_in, const int* in_sizes, int n_in,
                              void* d_out, int out_size) {
    const float* x      = (const float*)d_in[0];   // [8,256,128,128]
    const float* w_conv = (const float*)d_in[1];   // [2,256,3,3]
    const float* b_conv = (const float*)d_in[2];   // [2]
    float* out = (float*)d_out;                    // [8,256,128,128,1]

    offset_conv_partial<<<dim3(HH / 16, BB, CSPLIT), 256>>>(x, w_conv);
    offset_combine<<<NPIX / 256, 256>>>(b_conv);

    int total_threads = BB * (CC / 4) * HWc;       // 8,388,608
    bilinear_sample_kernel<<<total_threads / 256, 256>>>(x, out);
}

// round 15
// speedup vs baseline: 4.9748x; 1.0032x over previous
#include <cuda_runtime.h>

// Problem constants
#define BB 8
#define CC 256
#define HH 128
#define WW 128
#define HWc (HH * WW)      // 16384
#define NPIX (BB * HWc)    // 131072
#define CSPLIT 8
#define CPB (CC / CSPLIT)  // 32 channels per block

// Device scratch (no allocs allowed).
__device__ float g_part0[CSPLIT * NPIX];   // 4 MB
__device__ float g_part1[CSPLIT * NPIX];   // 4 MB
__device__ float g_px[NPIX];
__device__ float g_py[NPIX];

// ---- packed f32x2 helpers (sm_103a FFMA2 is PTX-only) ----------------------
__device__ __forceinline__ unsigned long long pack_dup(float x) {
    unsigned long long r;
    asm("mov.b64 %0, {%1, %1};" : "=l"(r) : "r"(__float_as_uint(x)));
    return r;
}
__device__ __forceinline__ void unpack2(unsigned long long v, float& lo, float& hi) {
    unsigned int a, b;
    asm("mov.b64 {%0, %1}, %2;" : "=r"(a), "=r"(b) : "l"(v));
    lo = __uint_as_float(a);
    hi = __uint_as_float(b);
}
#define FMA2(acc, a, b) \
    asm("fma.rn.f32x2 %0, %1, %2, %0;" : "+l"(acc) : "l"(a), "l"(b))

// ---------------------------------------------------------------------------
// Kernel A: offset conv partials, software-pipelined.
// grid=(H/16, B, CSPLIT)=(8,8,8), block=256. Thread (txl=tid&15, ty=tid>>4)
// computes 8 adjacent-w pixels of row h0+ty for 32 channels.
// Double-buffered smem channel-pair tiles (18 rows x 136 padded cols):
//   iter i: LDG pair i+1 -> regs | compute pair i | BAR | STS regs | BAR.
// Row layout: [3]=col -1 (zero), [4..131]=cols 0..127, [132]=col 128 (zero).
// ---------------------------------------------------------------------------
__global__ __launch_bounds__(256)
void offset_conv_partial(const float* __restrict__ x,
                         const float* __restrict__ w_conv) {
    __shared__ __align__(16) float  xt[2][2][18][136];  // ~39 KB
    __shared__ __align__(16) float2 ws2[CPB][9];        // (w0,w1) pairs

    const int tid = threadIdx.x;
    const int txl = tid & 15;    // w-group of 8 pixels
    const int ty  = tid >> 4;    // row 0..15
    const int h0  = blockIdx.x * 16;
    const int b   = blockIdx.y;
    const int c0  = blockIdx.z * CPB;

    // Stage packed weights. w_conv flat: o*2304 + c*9 + k
    // NOTE: CPB*9 = 288 > blockDim, must be a strided loop (R13 bug).
    for (int i = tid; i < CPB * 9; i += 256) {
        int c = i / 9, k = i - c * 9;
        ws2[c][k] = make_float2(w_conv[(c0 + c) * 9 + k],
                                w_conv[2304 + (c0 + c) * 9 + k]);
    }
    // Column-halo zeros (cols -1 and 128 are always outside the image).
    if (tid < 144) {
        int bf  = tid / 72;
        int rem = tid - bf * 72;
        int ch  = rem / 36; rem -= ch * 36;
        int r = rem >> 1, side = rem & 1;
        xt[bf][ch][r][side ? 132 : 3] = 0.f;
    }

    const float* xb = x + (((size_t)b * CC + c0) << 14);

    // Per-thread constant prefetch slots (division-free decode).
    int  pr_r[5], pr_c4[5], pr_ch[5];
    bool pr_v[5], pr_g[5];
    #pragma unroll
    for (int k = 0; k < 5; k++) {
        int idx = tid + (k << 8);          // 0..1279 over 2ch x 18rows x 32 float4
        pr_v[k] = idx < 1152;
        int ch = idx >= 576 ? 1 : 0;
        int ii = idx - ch * 576;
        pr_r[k]  = ii >> 5;
        pr_c4[k] = ii & 31;
        pr_ch[k] = ch;
        int gh = h0 - 1 + pr_r[k];
        pr_g[k] = pr_v[k] && ((unsigned)gh < HH);
    }

    float4 pre[5];
    auto load_pair = [&](int pair) {
        const float* base = xb + ((size_t)(pair * 2) << 14);
        #pragma unroll
        for (int k = 0; k < 5; k++) {
            float4 v = make_float4(0.f, 0.f, 0.f, 0.f);
            if (pr_g[k]) {
                int gh = h0 - 1 + pr_r[k];
                v = *(const float4*)(base + ((size_t)pr_ch[k] << 14)
                                     + gh * WW + pr_c4[k] * 4);
            }
            pre[k] = v;
        }
    };
    auto store_pair = [&](int bf) {
        #pragma unroll
        for (int k = 0; k < 5; k++)
            if (pr_v[k])
                *(float4*)&xt[bf][pr_ch[k]][pr_r[k]][4 + pr_c4[k] * 4] = pre[k];
    };

    // Prologue: fill buffer 0 with channel pair 0.
    load_pair(0);
    store_pair(0);
    __syncthreads();

    unsigned long long accp[8] = {0ull,0ull,0ull,0ull,0ull,0ull,0ull,0ull};
    const int s = txl * 8;   // window float-index base (col w0-1 at row+s+3)

    for (int i = 0; i < CPB / 2; i++) {
        const int bf = i & 1;
        const bool more = (i + 1) < (CPB / 2);
        if (more) load_pair(i + 1);   // LDGs in flight during compute

        #pragma unroll
        for (int cc = 0; cc < 2; cc++) {
            const unsigned long long* wr =
                (const unsigned long long*)&ws2[2 * i + cc][0];
            #pragma unroll
            for (int r = 0; r < 3; r++) {
                // 3 broadcast weight pairs for this tap row
                unsigned long long w0 = wr[r * 3 + 0];
                unsigned long long w1 = wr[r * 3 + 1];
                unsigned long long w2 = wr[r * 3 + 2];

                const float* row = &xt[bf][cc][ty + r][0];
                float2 e0 = *(const float2*)(row + s + 2);   // .y = col w0-1
                float4 m0 = *(const float4*)(row + s + 4);
                float4 m1 = *(const float4*)(row + s + 8);
                float2 e1 = *(const float2*)(row + s + 12);  // .x = col w0+8

                unsigned long long pv[10];
                pv[0] = pack_dup(e0.y);
                pv[1] = pack_dup(m0.x); pv[2] = pack_dup(m0.y);
                pv[3] = pack_dup(m0.z); pv[4] = pack_dup(m0.w);
                pv[5] = pack_dup(m1.x); pv[6] = pack_dup(m1.y);
                pv[7] = pack_dup(m1.z); pv[8] = pack_dup(m1.w);
                pv[9] = pack_dup(e1.x);

                #pragma unroll
                for (int j = 0; j < 8; j++) {
                    FMA2(accp[j], w0, pv[j]);
                    FMA2(accp[j], w1, pv[j + 1]);
                    FMA2(accp[j], w2, pv[j + 2]);
                }
            }
        }
        __syncthreads();               // reads of xt[bf] complete
        if (more) store_pair(bf ^ 1);  // write next pair into the other buffer
        __syncthreads();
    }

    // Epilogue: unpack and store partials (2x float4 per array, coalesced).
    float o0[8], o1[8];
    #pragma unroll
    for (int j = 0; j < 8; j++) unpack2(accp[j], o0[j], o1[j]);

    const int h   = h0 + ty;
    const int pix = (b << 14) + h * WW + txl * 8;
    const int idx = blockIdx.z * NPIX + pix;
    *(float4*)&g_part0[idx]     = make_float4(o0[0], o0[1], o0[2], o0[3]);
    *(float4*)&g_part0[idx + 4] = make_float4(o0[4], o0[5], o0[6], o0[7]);
    *(float4*)&g_part1[idx]     = make_float4(o1[0], o1[1], o1[2], o1[3]);
    *(float4*)&g_part1[idx + 4] = make_float4(o1[4], o1[5], o1[6], o1[7]);
}

// ---------------------------------------------------------------------------
// Kernel A2: reduce the 8 channel-split partials, add bias, clip -> px/py.
// ---------------------------------------------------------------------------
__global__ __launch_bounds__(256)
void offset_combine(const float* __restrict__ b_conv) {
    int p = blockIdx.x * 256 + threadIdx.x;
    float s0 = 0.f, s1 = 0.f;
    #pragma unroll
    for (int s = 0; s < CSPLIT; s++) {
        s0 += g_part0[s * NPIX + p];
        s1 += g_part1[s * NPIX + p];
    }
    int h = (p >> 7) & (HH - 1);
    int w = p & (WW - 1);
    float px = (float)h + s0 + b_conv[0];
    float py = (float)w + s1 + b_conv[1];
    px = fminf(fmaxf(px, 0.f), (float)(HH - 2));
    py = fminf(fmaxf(py, 0.f), (float)(WW - 2));
    g_px[p] = px;
    g_py[p] = py;
}

// ---------------------------------------------------------------------------
// Kernel B: bilinear sampling (unchanged — L1-bound at 68us).
// ---------------------------------------------------------------------------
__global__ __launch_bounds__(256)
void bilinear_sample_kernel(const float* __restrict__ x,
                            float* __restrict__ out) {
    int gid  = blockIdx.x * 256 + threadIdx.x;
    int pix  = gid & (HWc - 1);
    int rest = gid >> 14;        // b*64 + cg
    int cg   = rest & 63;
    int b    = rest >> 6;

    float px = g_px[(b << 14) + pix];
    float py = g_py[(b << 14) + pix];

    float fx = floorf(px);
    float fy = floorf(py);
    float dx = px - fx;
    float dy = py - fy;
    int qx0 = (int)fx;
    int qy0 = (int)fy;

    size_t plane0 = ((size_t)b * CC + (cg << 2)) << 14;
    const float* xp = x + plane0 + (qx0 * WW + qy0);
    float* op = out + plane0 + pix;

    #pragma unroll
    for (int j = 0; j < 4; j++) {
        const float* p = xp + ((size_t)j << 14);
        float x00 = __ldg(p);
        float x01 = __ldg(p + 1);
        float x10 = __ldg(p + WW);
        float x11 = __ldg(p + WW + 1);
        float top = fmaf(dy, x01 - x00, x00);
        float bot = fmaf(dy, x11 - x10, x10);
        op[(size_t)j << 14] = fmaf(dx, bot - top, top);
    }
}

// ---------------------------------------------------------------------------
// Launch
// ---------------------------------------------------------------------------
extern "C" void kernel_launch(void* const* d_in, const int* in_sizes, int n_in,
                              void* d_out, int out_size) {
    const float* x      = (const float*)d_in[0];   // [8,256,128,128]
    const float* w_conv = (const float*)d_in[1];   // [2,256,3,3]
    const float* b_conv = (const float*)d_in[2];   // [2]
    float* out = (float*)d_out;                    // [8,256,128,128,1]

    offset_conv_partial<<<dim3(HH / 16, BB, CSPLIT), 256>>>(x, w_conv);
    offset_combine<<<NPIX / 256, 256>>>(b_conv);

    int total_threads = BB * (CC / 4) * HWc;       // 8,388,608
    bilinear_sample_kernel<<<total_threads / 256, 256>>>(x, out);
}

// round 16
// speedup vs baseline: 5.5764x; 1.1209x over previous
#include <cuda_runtime.h>
#include <cstdint>

// Problem constants
#define BB 8
#define CC 256
#define HH 128
#define WW 128
#define HWc (HH * WW)      // 16384
#define NPIX (BB * HWc)    // 131072
#define CSPLIT 16
#define CPB (CC / CSPLIT)  // 16 channels per block

// Device scratch (no allocs allowed).
__device__ float  g_part0[CSPLIT * NPIX];   // 8 MB
__device__ float  g_part1[CSPLIT * NPIX];   // 8 MB
__device__ float2 g_pxy[NPIX];              // packed (px,py)

// ---- packed f32x2 helpers (sm_103a FFMA2 is PTX-only) ----------------------
__device__ __forceinline__ unsigned long long pack_dup(float x) {
    unsigned long long r;
    asm("mov.b64 %0, {%1, %1};" : "=l"(r) : "r"(__float_as_uint(x)));
    return r;
}
__device__ __forceinline__ void unpack2(unsigned long long v, float& lo, float& hi) {
    unsigned int a, b;
    asm("mov.b64 {%0, %1}, %2;" : "=r"(a), "=r"(b) : "l"(v));
    lo = __uint_as_float(a);
    hi = __uint_as_float(b);
}
#define FMA2(acc, a, b) \
    asm("fma.rn.f32x2 %0, %1, %2, %0;" : "+l"(acc) : "l"(a), "l"(b))

// cp.async 16B with zero-fill (src_sz in {0,16}); .cg keeps x tiles out of L1.
__device__ __forceinline__ void cp_async16(uint32_t smem, const void* gmem, int src_sz) {
    asm volatile("cp.async.cg.shared.global [%0], [%1], 16, %2;"
                 :: "r"(smem), "l"(gmem), "r"(src_sz) : "memory");
}

// ---------------------------------------------------------------------------
// Kernel A: offset conv partials, cp.async double-buffered pipeline.
// grid=(H/16, B, CSPLIT)=(8,8,16), block=256. Thread (txl=tid&15, ty=tid>>4)
// computes 8 adjacent-w pixels of row h0+ty for 16 channels.
// Per iteration (channel pair): wait_group 0 -> BAR -> issue cp.async for
// pair i+1 into other buffer -> compute pair i. One barrier per iteration.
// Row layout: [3]=col -1 (zero), [4..131]=cols 0..127, [132]=col 128 (zero).
// ---------------------------------------------------------------------------
__global__ __launch_bounds__(256)
void offset_conv_partial(const float* __restrict__ x,
                         const float* __restrict__ w_conv) {
    __shared__ __align__(16) float  xt[2][2][18][136];  // ~39 KB
    __shared__ __align__(16) float2 ws2[CPB][9];        // (w0,w1) pairs

    const int tid = threadIdx.x;
    const int txl = tid & 15;    // w-group of 8 pixels
    const int ty  = tid >> 4;    // row 0..15
    const int h0  = blockIdx.x * 16;
    const int b   = blockIdx.y;
    const int c0  = blockIdx.z * CPB;

    // Stage packed weights. CPB*9 = 144 <= 256, single shot.
    if (tid < CPB * 9) {
        int c = tid / 9, k = tid - c * 9;
        ws2[c][k] = make_float2(w_conv[(c0 + c) * 9 + k],
                                w_conv[2304 + (c0 + c) * 9 + k]);
    }
    // Column-halo zeros (cols -1 and 128), both buffers, once.
    if (tid < 144) {
        int bf  = tid / 72;
        int rem = tid - bf * 72;
        int ch  = rem / 36; rem -= ch * 36;
        int r = rem >> 1, side = rem & 1;
        xt[bf][ch][r][side ? 132 : 3] = 0.f;
    }

    const float* xb = x + (((size_t)b * CC + c0) << 14);

    // Per-thread cp.async slots over 2ch x 18rows x 32 float4 = 1152 slots.
    uint32_t so[5];   // smem byte offset (buffer 0)
    int      go[5];   // gmem float offset within channel pair
    int      sz[5];   // 16 or 0 (zero-fill OOB rows)
    bool     vv[5];
    const uint32_t smem0 = (uint32_t)__cvta_generic_to_shared(&xt[0][0][0][0]);
    const uint32_t buf_stride = 2 * 18 * 136 * 4;   // bytes per buffer
    #pragma unroll
    for (int k = 0; k < 5; k++) {
        int idx = tid + (k << 8);
        vv[k] = idx < 1152;
        int ch = idx >= 576 ? 1 : 0;
        int ii = idx - ch * 576;
        int r  = ii >> 5;
        int c4 = ii & 31;
        int gh = h0 - 1 + r;
        bool inb = (unsigned)gh < HH;
        so[k] = smem0 + (((ch * 18 + r) * 136) + 4 + c4 * 4) * 4;
        go[k] = (ch << 14) + (inb ? gh * WW : 0) + c4 * 4;
        sz[k] = (vv[k] && inb) ? 16 : 0;
    }

    auto issue_pair = [&](int pair, int bf) {
        const float* base = xb + ((size_t)(pair * 2) << 14);
        uint32_t sb = bf * buf_stride;
        #pragma unroll
        for (int k = 0; k < 5; k++)
            if (vv[k]) cp_async16(so[k] + sb, base + go[k], sz[k]);
        asm volatile("cp.async.commit_group;" ::: "memory");
    };

    // Prologue: pair 0 -> buffer 0.
    issue_pair(0, 0);

    unsigned long long accp[8] = {0ull,0ull,0ull,0ull,0ull,0ull,0ull,0ull};
    const int s = txl * 8;

    for (int i = 0; i < CPB / 2; i++) {
        const int bf = i & 1;
        asm volatile("cp.async.wait_group 0;" ::: "memory");
        __syncthreads();               // pair i visible; prev compute reads done
        if (i + 1 < CPB / 2) issue_pair(i + 1, bf ^ 1);

        #pragma unroll
        for (int cc = 0; cc < 2; cc++) {
            const unsigned long long* wr =
                (const unsigned long long*)&ws2[2 * i + cc][0];
            #pragma unroll
            for (int r = 0; r < 3; r++) {
                unsigned long long w0 = wr[r * 3 + 0];
                unsigned long long w1 = wr[r * 3 + 1];
                unsigned long long w2 = wr[r * 3 + 2];

                const float* row = &xt[bf][cc][ty + r][0];
                float2 e0 = *(const float2*)(row + s + 2);   // .y = col w0-1
                float4 m0 = *(const float4*)(row + s + 4);
                float4 m1 = *(const float4*)(row + s + 8);
                float2 e1 = *(const float2*)(row + s + 12);  // .x = col w0+8

                unsigned long long pv[10];
                pv[0] = pack_dup(e0.y);
                pv[1] = pack_dup(m0.x); pv[2] = pack_dup(m0.y);
                pv[3] = pack_dup(m0.z); pv[4] = pack_dup(m0.w);
                pv[5] = pack_dup(m1.x); pv[6] = pack_dup(m1.y);
                pv[7] = pack_dup(m1.z); pv[8] = pack_dup(m1.w);
                pv[9] = pack_dup(e1.x);

                #pragma unroll
                for (int j = 0; j < 8; j++) {
                    FMA2(accp[j], w0, pv[j]);
                    FMA2(accp[j], w1, pv[j + 1]);
                    FMA2(accp[j], w2, pv[j + 2]);
                }
            }
        }
    }

    // Epilogue: unpack and store partials (coalesced float4 x2 per array).
    float o0[8], o1[8];
    #pragma unroll
    for (int j = 0; j < 8; j++) unpack2(accp[j], o0[j], o1[j]);

    const int h   = h0 + ty;
    const int pix = (b << 14) + h * WW + txl * 8;
    const int idx = blockIdx.z * NPIX + pix;
    *(float4*)&g_part0[idx]     = make_float4(o0[0], o0[1], o0[2], o0[3]);
    *(float4*)&g_part0[idx + 4] = make_float4(o0[4], o0[5], o0[6], o0[7]);
    *(float4*)&g_part1[idx]     = make_float4(o1[0], o1[1], o1[2], o1[3]);
    *(float4*)&g_part1[idx + 4] = make_float4(o1[4], o1[5], o1[6], o1[7]);
}

// ---------------------------------------------------------------------------
// Kernel A2: reduce 16 channel-split partials, add bias, clip -> packed pxy.
// ---------------------------------------------------------------------------
__global__ __launch_bounds__(256)
void offset_combine(const float* __restrict__ b_conv) {
    int p = blockIdx.x * 256 + threadIdx.x;
    float s0 = 0.f, s1 = 0.f;
    #pragma unroll
    for (int s = 0; s < CSPLIT; s++) {
        s0 += g_part0[s * NPIX + p];
        s1 += g_part1[s * NPIX + p];
    }
    int h = (p >> 7) & (HH - 1);
    int w = p & (WW - 1);
    float px = (float)h + s0 + b_conv[0];
    float py = (float)w + s1 + b_conv[1];
    px = fminf(fmaxf(px, 0.f), (float)(HH - 2));
    py = fminf(fmaxf(py, 0.f), (float)(WW - 2));
    g_pxy[p] = make_float2(px, py);
}

// ---------------------------------------------------------------------------
// Kernel B: bilinear sampling, 8 consecutive channels per thread.
// Lanes differ in pix (adjacent w) -> coalesced coord reads/output stores;
// gathers span few lines since offsets are small.
// ---------------------------------------------------------------------------
__global__ __launch_bounds__(256)
void bilinear_sample_kernel(const float* __restrict__ x,
                            float* __restrict__ out) {
    int gid  = blockIdx.x * 256 + threadIdx.x;
    int pix  = gid & (HWc - 1);
    int rest = gid >> 14;        // b*32 + cg
    int cg   = rest & 31;
    int b    = rest >> 5;

    float2 pp = g_pxy[(b << 14) + pix];
    float px = pp.x, py = pp.y;

    float fx = floorf(px);
    float fy = floorf(py);
    float dx = px - fx;
    float dy = py - fy;
    int qx0 = (int)fx;
    int qy0 = (int)fy;

    size_t plane0 = ((size_t)b * CC + (cg << 3)) << 14;
    const float* xp = x + plane0 + (qx0 * WW + qy0);
    float* op = out + plane0 + pix;

    #pragma unroll
    for (int j = 0; j < 8; j++) {
        const float* p = xp + ((size_t)j << 14);
        float x00 = __ldg(p);
        float x01 = __ldg(p + 1);
        float x10 = __ldg(p + WW);
        float x11 = __ldg(p + WW + 1);
        float top = fmaf(dy, x01 - x00, x00);
        float bot = fmaf(dy, x11 - x10, x10);
        op[(size_t)j << 14] = fmaf(dx, bot - top, top);
    }
}

// ---------------------------------------------------------------------------
// Launch
// ---------------------------------------------------------------------------
extern "C" void kernel_launch(void* const* d_in, const int* in_sizes, int n_in,
                              void* d_out, int out_size) {
    const float* x      = (const float*)d_in[0];   // [8,256,128,128]
    const float* w_conv = (const float*)d_in[1];   // [2,256,3,3]
    const float* b_conv = (const float*)d_in[2];   // [2]
    float* out = (float*)d_out;                    // [8,256,128,128,1]

    offset_conv_partial<<<dim3(HH / 16, BB, CSPLIT), 256>>>(x, w_conv);
    offset_combine<<<NPIX / 256, 256>>>(b_conv);

    int total_threads = BB * (CC / 8) * HWc;       // 4,194,304
    bilinear_sample_kernel<<<total_threads / 256, 256>>>(x, out);
}

// round 17
// speedup vs baseline: 5.5778x; 1.0003x over previous
#include <cuda_runtime.h>
#include <cstdint>

// Problem constants
#define BB 8
#define CC 256
#define HH 128
#define WW 128
#define HWc (HH * WW)      // 16384
#define NPIX (BB * HWc)    // 131072
#define CSPLIT 16
#define CPB (CC / CSPLIT)  // 16 channels per block

// Device scratch (no allocs allowed).
__device__ float  g_part0[CSPLIT * NPIX];   // 8 MB
__device__ float  g_part1[CSPLIT * NPIX];   // 8 MB
__device__ float2 g_pxy[NPIX];              // packed (px,py)

// ---- packed f32x2 helpers (sm_103a FFMA2 is PTX-only) ----------------------
__device__ __forceinline__ unsigned long long pack_dup(float x) {
    unsigned long long r;
    asm("mov.b64 %0, {%1, %1};" : "=l"(r) : "r"(__float_as_uint(x)));
    return r;
}
__device__ __forceinline__ void unpack2(unsigned long long v, float& lo, float& hi) {
    unsigned int a, b;
    asm("mov.b64 {%0, %1}, %2;" : "=r"(a), "=r"(b) : "l"(v));
    lo = __uint_as_float(a);
    hi = __uint_as_float(b);
}
#define FMA2(acc, a, b) \
    asm("fma.rn.f32x2 %0, %1, %2, %0;" : "+l"(acc) : "l"(a), "l"(b))

// cp.async 16B with zero-fill (src_sz in {0,16}); .cg keeps x tiles out of L1.
__device__ __forceinline__ void cp_async16(uint32_t smem, const void* gmem, int src_sz) {
    asm volatile("cp.async.cg.shared.global [%0], [%1], 16, %2;"
                 :: "r"(smem), "l"(gmem), "r"(src_sz) : "memory");
}

// ---------------------------------------------------------------------------
// Kernel A: offset conv partials, cp.async double-buffered pipeline.
// grid=(H/16, B, CSPLIT)=(8,8,16), block=256. Thread (txl=tid&15, ty=tid>>4)
// computes 8 adjacent-w pixels of row h0+ty for 16 channels.
// Per iteration (channel pair): wait_group 0 -> BAR -> issue cp.async for
// pair i+1 into other buffer -> compute pair i. One barrier per iteration.
// Row layout: [3]=col -1 (zero), [4..131]=cols 0..127, [132]=col 128 (zero).
// ---------------------------------------------------------------------------
__global__ __launch_bounds__(256)
void offset_conv_partial(const float* __restrict__ x,
                         const float* __restrict__ w_conv) {
    __shared__ __align__(16) float  xt[2][2][18][136];  // ~39 KB
    __shared__ __align__(16) float2 ws2[CPB][9];        // (w0,w1) pairs

    const int tid = threadIdx.x;
    const int txl = tid & 15;    // w-group of 8 pixels
    const int ty  = tid >> 4;    // row 0..15
    const int h0  = blockIdx.x * 16;
    const int b   = blockIdx.y;
    const int c0  = blockIdx.z * CPB;

    // Stage packed weights. CPB*9 = 144 <= 256, single shot.
    if (tid < CPB * 9) {
        int c = tid / 9, k = tid - c * 9;
        ws2[c][k] = make_float2(w_conv[(c0 + c) * 9 + k],
                                w_conv[2304 + (c0 + c) * 9 + k]);
    }
    // Column-halo zeros (cols -1 and 128), both buffers, once.
    if (tid < 144) {
        int bf  = tid / 72;
        int rem = tid - bf * 72;
        int ch  = rem / 36; rem -= ch * 36;
        int r = rem >> 1, side = rem & 1;
        xt[bf][ch][r][side ? 132 : 3] = 0.f;
    }

    const float* xb = x + (((size_t)b * CC + c0) << 14);

    // Per-thread cp.async slots over 2ch x 18rows x 32 float4 = 1152 slots.
    uint32_t so[5];   // smem byte offset (buffer 0)
    int      go[5];   // gmem float offset within channel pair
    int      sz[5];   // 16 or 0 (zero-fill OOB rows)
    bool     vv[5];
    const uint32_t smem0 = (uint32_t)__cvta_generic_to_shared(&xt[0][0][0][0]);
    const uint32_t buf_stride = 2 * 18 * 136 * 4;   // bytes per buffer
    #pragma unroll
    for (int k = 0; k < 5; k++) {
        int idx = tid + (k << 8);
        vv[k] = idx < 1152;
        int ch = idx >= 576 ? 1 : 0;
        int ii = idx - ch * 576;
        int r  = ii >> 5;
        int c4 = ii & 31;
        int gh = h0 - 1 + r;
        bool inb = (unsigned)gh < HH;
        so[k] = smem0 + (((ch * 18 + r) * 136) + 4 + c4 * 4) * 4;
        go[k] = (ch << 14) + (inb ? gh * WW : 0) + c4 * 4;
        sz[k] = (vv[k] && inb) ? 16 : 0;
    }

    auto issue_pair = [&](int pair, int bf) {
        const float* base = xb + ((size_t)(pair * 2) << 14);
        uint32_t sb = bf * buf_stride;
        #pragma unroll
        for (int k = 0; k < 5; k++)
            if (vv[k]) cp_async16(so[k] + sb, base + go[k], sz[k]);
        asm volatile("cp.async.commit_group;" ::: "memory");
    };

    // Prologue: pair 0 -> buffer 0.
    issue_pair(0, 0);

    unsigned long long accp[8] = {0ull,0ull,0ull,0ull,0ull,0ull,0ull,0ull};
    const int s = txl * 8;

    for (int i = 0; i < CPB / 2; i++) {
        const int bf = i & 1;
        asm volatile("cp.async.wait_group 0;" ::: "memory");
        __syncthreads();               // pair i visible; prev compute reads done
        if (i + 1 < CPB / 2) issue_pair(i + 1, bf ^ 1);

        #pragma unroll
        for (int cc = 0; cc < 2; cc++) {
            const unsigned long long* wr =
                (const unsigned long long*)&ws2[2 * i + cc][0];
            #pragma unroll
            for (int r = 0; r < 3; r++) {
                unsigned long long w0 = wr[r * 3 + 0];
                unsigned long long w1 = wr[r * 3 + 1];
                unsigned long long w2 = wr[r * 3 + 2];

                const float* row = &xt[bf][cc][ty + r][0];
                float2 e0 = *(const float2*)(row + s + 2);   // .y = col w0-1
                float4 m0 = *(const float4*)(row + s + 4);
                float4 m1 = *(const float4*)(row + s + 8);
                float2 e1 = *(const float2*)(row + s + 12);  // .x = col w0+8

                unsigned long long pv[10];
                pv[0] = pack_dup(e0.y);
                pv[1] = pack_dup(m0.x); pv[2] = pack_dup(m0.y);
                pv[3] = pack_dup(m0.z); pv[4] = pack_dup(m0.w);
                pv[5] = pack_dup(m1.x); pv[6] = pack_dup(m1.y);
                pv[7] = pack_dup(m1.z); pv[8] = pack_dup(m1.w);
                pv[9] = pack_dup(e1.x);

                #pragma unroll
                for (int j = 0; j < 8; j++) {
                    FMA2(accp[j], w0, pv[j]);
                    FMA2(accp[j], w1, pv[j + 1]);
                    FMA2(accp[j], w2, pv[j + 2]);
                }
            }
        }
    }

    // Epilogue: unpack and store partials (coalesced float4 x2 per array).
    float o0[8], o1[8];
    #pragma unroll
    for (int j = 0; j < 8; j++) unpack2(accp[j], o0[j], o1[j]);

    const int h   = h0 + ty;
    const int pix = (b << 14) + h * WW + txl * 8;
    const int idx = blockIdx.z * NPIX + pix;
    *(float4*)&g_part0[idx]     = make_float4(o0[0], o0[1], o0[2], o0[3]);
    *(float4*)&g_part0[idx + 4] = make_float4(o0[4], o0[5], o0[6], o0[7]);
    *(float4*)&g_part1[idx]     = make_float4(o1[0], o1[1], o1[2], o1[3]);
    *(float4*)&g_part1[idx + 4] = make_float4(o1[4], o1[5], o1[6], o1[7]);
}

// ---------------------------------------------------------------------------
// Kernel A2: reduce 16 channel-split partials, add bias, clip -> packed pxy.
// ---------------------------------------------------------------------------
__global__ __launch_bounds__(256)
void offset_combine(const float* __restrict__ b_conv) {
    int p = blockIdx.x * 256 + threadIdx.x;
    float s0 = 0.f, s1 = 0.f;
    #pragma unroll
    for (int s = 0; s < CSPLIT; s++) {
        s0 += g_part0[s * NPIX + p];
        s1 += g_part1[s * NPIX + p];
    }
    int h = (p >> 7) & (HH - 1);
    int w = p & (WW - 1);
    float px = (float)h + s0 + b_conv[0];
    float py = (float)w + s1 + b_conv[1];
    px = fminf(fmaxf(px, 0.f), (float)(HH - 2));
    py = fminf(fmaxf(py, 0.f), (float)(WW - 2));
    g_pxy[p] = make_float2(px, py);
}

// ---------------------------------------------------------------------------
// Kernel B: bilinear sampling, 8 consecutive channels per thread.
// Lanes differ in pix (adjacent w) -> coalesced coord reads/output stores;
// gathers span few lines since offsets are small.
// ---------------------------------------------------------------------------
__global__ __launch_bounds__(256)
void bilinear_sample_kernel(const float* __restrict__ x,
                            float* __restrict__ out) {
    int gid  = blockIdx.x * 256 + threadIdx.x;
    int pix  = gid & (HWc - 1);
    int rest = gid >> 14;        // b*32 + cg
    int cg   = rest & 31;
    int b    = rest >> 5;

    float2 pp = g_pxy[(b << 14) + pix];
    float px = pp.x, py = pp.y;

    float fx = floorf(px);
    float fy = floorf(py);
    float dx = px - fx;
    float dy = py - fy;
    int qx0 = (int)fx;
    int qy0 = (int)fy;

    size_t plane0 = ((size_t)b * CC + (cg << 3)) << 14;
    const float* xp = x + plane0 + (qx0 * WW + qy0);
    float* op = out + plane0 + pix;

    #pragma unroll
    for (int j = 0; j < 8; j++) {
        const float* p = xp + ((size_t)j << 14);
        float x00 = __ldg(p);
        float x01 = __ldg(p + 1);
        float x10 = __ldg(p + WW);
        float x11 = __ldg(p + WW + 1);
        float top = fmaf(dy, x01 - x00, x00);
        float bot = fmaf(dy, x11 - x10, x10);
        op[(size_t)j << 14] = fmaf(dx, bot - top, top);
    }
}

// ---------------------------------------------------------------------------
// Launch
// ---------------------------------------------------------------------------
extern "C" void kernel_launch(void* const* d_in, const int* in_sizes, int n_in,
                              void* d_out, int out_size) {
    const float* x      = (const float*)d_in[0];   // [8,256,128,128]
    const float* w_conv = (const float*)d_in[1];   // [2,256,3,3]
    const float* b_conv = (const float*)d_in[2];   // [2]
    float* out = (float*)d_out;                    // [8,256,128,128,1]

    offset_conv_partial<<<dim3(HH / 16, BB, CSPLIT), 256>>>(x, w_conv);
    offset_combine<<<NPIX / 256, 256>>>(b_conv);

    int total_threads = BB * (CC / 8) * HWc;       // 4,194,304
    bilinear_sample_kernel<<<total_threads / 256, 256>>>(x, out);
}